// round 1
// baseline (speedup 1.0000x reference)
#include <cuda_runtime.h>

// Problem constants: x[B=16, S=2048], emb[V=7, E=128], fc_w[E=128, W*E=16384],
// fc_b[128], out_w[1,128], out_b[1]. Output: [16] float32.
#define Ec 128
#define Wc 128
#define Vc 7
#define Sc 2048
#define Bc 16

// Scratch (no allocations allowed in kernel_launch)
__device__ float d_g[Ec * Wc];   // g[e*W + k] = sum_o out_w[o] * fc_w[o, e*W+k]
__device__ float d_T[Vc * Wc];   // T[v, k]    = sum_e emb[v,e] * g[e*W+k]
__device__ int   d_is32;         // 1 if x buffer is int32, 0 if int64

// ---------------------------------------------------------------------------
// Detect x dtype. Tokens are in [0,7). If x is int64, every odd 32-bit word
// (the high half) is zero. If x is int32, odd words are tokens at odd seq
// positions; over 16384 samples the chance they're all zero is ~(1/7)^16384.
// Scan only the first 32768 words: safe for both layouts (int32 buffer is
// exactly 32768 words; int64 buffer is 65536).
// ---------------------------------------------------------------------------
__global__ void detect_kernel(const int* __restrict__ xw) {
    __shared__ int sw[32];
    int any = 0;
    for (int i = threadIdx.x; i < 32768; i += blockDim.x)
        if ((i & 1) && xw[i] != 0) any = 1;
    any = __any_sync(0xffffffffu, any) ? 1 : 0;
    if ((threadIdx.x & 31) == 0) sw[threadIdx.x >> 5] = any;
    __syncthreads();
    if (threadIdx.x == 0) {
        int a = 0;
        int nw = blockDim.x >> 5;
        for (int i = 0; i < nw; i++) a |= sw[i];
        d_is32 = a;
    }
}

// ---------------------------------------------------------------------------
// g[j] = sum_o out_w[o] * fc_w[o*16384 + j].  Streams the full 8 MB of fc_w
// exactly once, fully coalesced (each warp reads a contiguous 128B line per o).
// ---------------------------------------------------------------------------
__global__ void g_kernel(const float* __restrict__ fc_w,
                         const float* __restrict__ out_w) {
    int j = blockIdx.x * blockDim.x + threadIdx.x;   // 0..16383
    float acc = 0.0f;
#pragma unroll 16
    for (int o = 0; o < Ec; o++)
        acc = fmaf(__ldg(&out_w[o]), fc_w[(size_t)o * (Ec * Wc) + j], acc);
    d_g[j] = acc;
}

// ---------------------------------------------------------------------------
// T[v,k] = sum_e emb[v,e] * g[e*W + k].  7 blocks x 128 threads; g hits L2.
// ---------------------------------------------------------------------------
__global__ void T_kernel(const float* __restrict__ emb) {
    int v = blockIdx.x;      // 0..6
    int k = threadIdx.x;     // 0..127
    float acc = 0.0f;
#pragma unroll 16
    for (int e = 0; e < Ec; e++)
        acc = fmaf(__ldg(&emb[v * Ec + e]), d_g[e * Wc + k], acc);
    d_T[v * Wc + k] = acc;
}

// ---------------------------------------------------------------------------
// Per batch: count non-pad tokens -> t = cnt-1; then
// out[b] = out_b + dot(out_w, fc_b) + sum_k [p=t-127+k >= 0] T[x[b,p], k]
// One block of 128 threads per batch (thread index == k == embedding index).
// ---------------------------------------------------------------------------
__global__ void final_kernel(const void* __restrict__ xraw,
                             const float* __restrict__ fc_b,
                             const float* __restrict__ out_w,
                             const float* __restrict__ out_b,
                             float* __restrict__ out) {
    const int b = blockIdx.x;
    const int k = threadIdx.x;               // 0..127
    const bool is32 = (d_is32 != 0);
    const int*       x32 = (const int*)xraw;
    const long long* x64 = (const long long*)xraw;

    // 1) count non-pad tokens in this batch row
    int cnt = 0;
    for (int s = k; s < Sc; s += Wc) {
        long long tok = is32 ? (long long)x32[b * Sc + s] : x64[b * Sc + s];
        cnt += (tok != 0);
    }
#pragma unroll
    for (int off = 16; off; off >>= 1)
        cnt += __shfl_down_sync(0xffffffffu, cnt, off);
    __shared__ int scnt[4];
    if ((k & 31) == 0) scnt[k >> 5] = cnt;
    __syncthreads();
    const int t = (scnt[0] + scnt[1] + scnt[2] + scnt[3]) - 1;

    // 2) window gather-sum + folded bias term (thread k contributes
    //    out_w[k]*fc_b[k] so the block reduction yields dot(out_w, fc_b))
    float acc = out_w[k] * fc_b[k];
    const int p = t - (Wc - 1) + k;
    if (p >= 0) {
        int tok = is32 ? x32[b * Sc + p] : (int)x64[b * Sc + p];
        acc += d_T[tok * Wc + k];
    }
#pragma unroll
    for (int off = 16; off; off >>= 1)
        acc += __shfl_down_sync(0xffffffffu, acc, off);
    __shared__ float sacc[4];
    if ((k & 31) == 0) sacc[k >> 5] = acc;
    __syncthreads();
    if (k == 0)
        out[b] = sacc[0] + sacc[1] + sacc[2] + sacc[3] + out_b[0];
}

extern "C" void kernel_launch(void* const* d_in, const int* in_sizes, int n_in,
                              void* d_out, int out_size) {
    const void*  x     = d_in[0];                      // [16,2048] int64 or int32
    const float* emb   = (const float*)d_in[1];        // [7,128]
    const float* fc_w  = (const float*)d_in[2];        // [128,16384]
    const float* fc_b  = (const float*)d_in[3];        // [128]
    const float* out_w = (const float*)d_in[4];        // [1,128]
    const float* out_b = (const float*)d_in[5];        // [1]
    float* out = (float*)d_out;                        // [16]

    detect_kernel<<<1, 1024>>>((const int*)x);
    g_kernel<<<(Ec * Wc) / 128, 128>>>(fc_w, out_w);
    T_kernel<<<Vc, Wc>>>(emb);
    final_kernel<<<Bc, Wc>>>(x, fc_b, out_w, out_b, out);
}

// round 2
// speedup vs baseline: 1.4116x; 1.4116x over previous
#include <cuda_runtime.h>

#define Ec 128
#define Wc 128
#define Vc 7
#define Sc 2048
#define Bc 16
#define GBLK 64          // blocks computing g in K1
#define K1T  256         // K1 block size

// Scratch
__device__ float d_g[Ec * Wc];   // g[e*W + k] = sum_o out_w[o] * fc_w[o, e*W+k]
__device__ int   d_cnt[Bc];      // per-batch non-pad count
__device__ int   d_is32;         // 1 if x is int32, 0 if int64

// ---------------------------------------------------------------------------
// K1: blocks [0,64) -> g[j] = sum_o out_w[o]*fc_w[o*16384+j]   (8MB stream)
//     blocks [64,80) -> per-batch token count (+ dtype self-detection)
// Dtype detection: tokens in [0,7). int64 => every odd 32-bit word is the
// (zero) high half. Scan first 2048 words (1024 odd samples): if any odd word
// is nonzero, layout is int32. P(miss) = (1/7)^1024 ~ 0. The first 8KB is
// in-bounds for both layouts (min buffer = 128KB for int32).
// ---------------------------------------------------------------------------
__global__ void k1_kernel(const float* __restrict__ fc_w,
                          const float* __restrict__ out_w,
                          const int*   __restrict__ xw) {
    const int blk = blockIdx.x;
    if (blk < GBLK) {
        const int j = blk * K1T + threadIdx.x;      // 0..16383
        float acc = 0.0f;
#pragma unroll 32
        for (int o = 0; o < Ec; o++)
            acc = fmaf(__ldg(&out_w[o]), fc_w[o * (Ec * Wc) + j], acc);
        d_g[j] = acc;
        return;
    }

    // ---- counting role ----
    const int b = blk - GBLK;                        // 0..15
    __shared__ int sred[K1T / 32];

    // 1) dtype detection over first 2048 words
    int any = 0;
#pragma unroll
    for (int i = threadIdx.x; i < 2048; i += K1T)
        if ((i & 1) && xw[i] != 0) any = 1;
    any = __any_sync(0xffffffffu, any) ? 1 : 0;
    if ((threadIdx.x & 31) == 0) sred[threadIdx.x >> 5] = any;
    __syncthreads();
    int is32 = 0;
#pragma unroll
    for (int i = 0; i < K1T / 32; i++) is32 |= sred[i];
    __syncthreads();

    // 2) count non-pad tokens in row b (8 coalesced loads per thread)
    int cnt = 0;
    if (is32) {
        const int* x32 = xw + b * Sc;
#pragma unroll
        for (int s = threadIdx.x; s < Sc; s += K1T) cnt += (x32[s] != 0);
    } else {
        const long long* x64 = (const long long*)xw + b * Sc;
#pragma unroll
        for (int s = threadIdx.x; s < Sc; s += K1T) cnt += (x64[s] != 0);
    }
#pragma unroll
    for (int off = 16; off; off >>= 1)
        cnt += __shfl_down_sync(0xffffffffu, cnt, off);
    if ((threadIdx.x & 31) == 0) sred[threadIdx.x >> 5] = cnt;
    __syncthreads();
    if (threadIdx.x == 0) {
        int c = 0;
#pragma unroll
        for (int i = 0; i < K1T / 32; i++) c += sred[i];
        d_cnt[b] = c;
        if (b == 0) d_is32 = is32;
    }
}

// ---------------------------------------------------------------------------
// K2: one block per batch, thread k = window tap k (= fc_b/out_w index).
// out[b] = out_b + dot(out_w, fc_b) + sum_k [p>=0] sum_e emb[x[b,p],e]*g[e*W+k]
// where p = (cnt[b]-1) - 127 + k. emb staged in shared with stride 129 to
// avoid the 128-stride bank conflict; g read from L2 (written by K1).
// ---------------------------------------------------------------------------
__global__ void k2_kernel(const void* __restrict__ xraw,
                          const float* __restrict__ emb,
                          const float* __restrict__ fc_b,
                          const float* __restrict__ out_w,
                          const float* __restrict__ out_b,
                          float* __restrict__ out) {
    const int b = blockIdx.x;
    const int k = threadIdx.x;                       // 0..127
    __shared__ float s_emb[Vc * 129];
    __shared__ float sacc[4];

    // stage emb [7,128] -> shared, padded stride 129
    for (int i = k; i < Vc * Ec; i += Wc)
        s_emb[(i >> 7) * 129 + (i & 127)] = emb[i];

    const int t = d_cnt[b] - 1;
    const int is32 = d_is32;
    const int p = t - (Wc - 1) + k;

    float acc = out_w[k] * fc_b[k];
    if (p >= 0) {
        int tok = is32 ? ((const int*)xraw)[b * Sc + p]
                       : (int)((const long long*)xraw)[b * Sc + p];
        const float* er = &s_emb[tok * 129];
        __syncthreads();   // emb staged (only threads entering here need it)
        float a0 = 0.f, a1 = 0.f;
#pragma unroll
        for (int e = 0; e < Ec; e += 2) {
            a0 = fmaf(er[e],     d_g[e * Wc + k],       a0);
            a1 = fmaf(er[e + 1], d_g[(e + 1) * Wc + k], a1);
        }
        acc += a0 + a1;
    } else {
        __syncthreads();
    }

    // block reduction over k
#pragma unroll
    for (int off = 16; off; off >>= 1)
        acc += __shfl_down_sync(0xffffffffu, acc, off);
    if ((k & 31) == 0) sacc[k >> 5] = acc;
    __syncthreads();
    if (k == 0)
        out[b] = sacc[0] + sacc[1] + sacc[2] + sacc[3] + out_b[0];
}

extern "C" void kernel_launch(void* const* d_in, const int* in_sizes, int n_in,
                              void* d_out, int out_size) {
    const void*  x     = d_in[0];                      // [16,2048] int64 or int32
    const float* emb   = (const float*)d_in[1];        // [7,128]
    const float* fc_w  = (const float*)d_in[2];        // [128,16384]
    const float* fc_b  = (const float*)d_in[3];        // [128]
    const float* out_w = (const float*)d_in[4];        // [1,128]
    const float* out_b = (const float*)d_in[5];        // [1]
    float* out = (float*)d_out;                        // [16]

    k1_kernel<<<GBLK + Bc, K1T>>>(fc_w, out_w, (const int*)x);
    k2_kernel<<<Bc, Wc>>>(x, emb, fc_b, out_w, out_b, out);
}

// round 3
// speedup vs baseline: 1.6054x; 1.1373x over previous
#include <cuda_runtime.h>

#define Ec   128
#define Wc   128
#define Vc   7
#define Sc   2048
#define Bc   16
#define GBLK 128                 // g-producer blocks (one per e-row)
#define NT   128                 // threads per block

// Scratch (module zero-initialized; counters reset at end of every run)
__device__ float d_g[Ec * Wc];
__device__ int   d_arrive;       // g-blocks completed
__device__ int   d_done;         // final blocks completed

__global__ void __launch_bounds__(NT, 1)
fused_kernel(const void* __restrict__ xraw,
             const float* __restrict__ emb,
             const float* __restrict__ fc_w,
             const float* __restrict__ fc_b,
             const float* __restrict__ out_w,
             const float* __restrict__ out_b,
             float* __restrict__ out) {
    const int blk = blockIdx.x;
    const int tid = threadIdx.x;

    if (blk < GBLK) {
        // ---------------- g producer: row e = blk ----------------
        const int e = blk;
        const int j = e * Wc + tid;
        __shared__ float s_w[Ec];
        s_w[tid] = out_w[tid];
        __syncthreads();
        float acc = 0.0f;
#pragma unroll 32
        for (int o = 0; o < Ec; o++)
            acc = fmaf(s_w[o], fc_w[o * (Ec * Wc) + j], acc);
        d_g[j] = acc;
        __threadfence();
        __syncthreads();
        if (tid == 0) atomicAdd(&d_arrive, 1);
        return;
    }

    // ---------------- final block: batch b = blk - GBLK ----------------
    const int b = blk - GBLK;
    const int k = tid;                                   // 0..127 = window tap
    __shared__ float s_emb[Vc * 129];
    __shared__ int   sred[NT / 32];
    __shared__ float sacc[NT / 32];

    // stage emb [7,128] -> shared (pad 129). Bank per read: (tok+e)%32, no conflict.
    for (int i = k; i < Vc * Ec; i += NT)
        s_emb[(i >> 7) * 129 + (i & 127)] = emb[i];

    // dtype detection (tokens in [0,7): int64 => all odd 32-bit words zero).
    // First 2048 words (8KB) are in-bounds for both layouts.
    const int* xw = (const int*)xraw;
    int any = 0;
#pragma unroll
    for (int i = k; i < 2048; i += NT)
        if ((i & 1) && xw[i] != 0) any = 1;
    any = __any_sync(0xffffffffu, any) ? 1 : 0;
    if ((k & 31) == 0) sred[k >> 5] = any;
    __syncthreads();
    const int is32 = sred[0] | sred[1] | sred[2] | sred[3];
    __syncthreads();

    // count non-pad tokens in row b
    int cnt = 0;
    if (is32) {
        const int* xr = (const int*)xraw + b * Sc;
#pragma unroll
        for (int s = k; s < Sc; s += NT) cnt += (xr[s] != 0);
    } else {
        const long long* xr = (const long long*)xraw + b * Sc;
#pragma unroll
        for (int s = k; s < Sc; s += NT) cnt += (xr[s] != 0);
    }
#pragma unroll
    for (int off = 16; off; off >>= 1)
        cnt += __shfl_down_sync(0xffffffffu, cnt, off);
    if ((k & 31) == 0) sred[k >> 5] = cnt;
    __syncthreads();
    const int t = (sred[0] + sred[1] + sred[2] + sred[3]) - 1;

    // issue dependent token load BEFORE the spin (overlaps g-phase DRAM)
    const int p = t - (Wc - 1) + k;
    int tok = -1;
    if (p >= 0)
        tok = is32 ? ((const int*)xraw)[b * Sc + p]
                   : (int)((const long long*)xraw)[b * Sc + p];

    // wait for all g rows
    if (tid == 0) {
        while (*(volatile int*)&d_arrive < GBLK) __nanosleep(32);
    }
    __syncthreads();
    __threadfence();   // acquire: make d_g writes visible

    float acc = out_w[k] * fc_b[k];
    if (tok >= 0) {
        const float* er = &s_emb[tok * 129];
        float a0 = 0.f, a1 = 0.f, a2 = 0.f, a3 = 0.f;
#pragma unroll
        for (int e = 0; e < Ec; e += 4) {
            a0 = fmaf(er[e],     d_g[(e)     * Wc + k], a0);
            a1 = fmaf(er[e + 1], d_g[(e + 1) * Wc + k], a1);
            a2 = fmaf(er[e + 2], d_g[(e + 2) * Wc + k], a2);
            a3 = fmaf(er[e + 3], d_g[(e + 3) * Wc + k], a3);
        }
        acc += (a0 + a1) + (a2 + a3);
    }

#pragma unroll
    for (int off = 16; off; off >>= 1)
        acc += __shfl_down_sync(0xffffffffu, acc, off);
    if ((k & 31) == 0) sacc[k >> 5] = acc;
    __syncthreads();
    if (k == 0)
        out[b] = sacc[0] + sacc[1] + sacc[2] + sacc[3] + out_b[0];

    // reset counters for the next graph replay (deterministic state)
    __threadfence();
    if (k == 0) {
        int d = atomicAdd(&d_done, 1);
        if (d == Bc - 1) {           // last final block; all spins already passed
            d_arrive = 0;
            d_done   = 0;
            __threadfence();
        }
    }
}

extern "C" void kernel_launch(void* const* d_in, const int* in_sizes, int n_in,
                              void* d_out, int out_size) {
    const void*  x     = d_in[0];                      // [16,2048] int64 or int32
    const float* emb   = (const float*)d_in[1];        // [7,128]
    const float* fc_w  = (const float*)d_in[2];        // [128,16384]
    const float* fc_b  = (const float*)d_in[3];        // [128]
    const float* out_w = (const float*)d_in[4];        // [1,128]
    const float* out_b = (const float*)d_in[5];        // [1]
    float* out = (float*)d_out;                        // [16]

    fused_kernel<<<GBLK + Bc, NT>>>(x, emb, fc_w, fc_b, out_w, out_b, out);
}